// round 17
// baseline (speedup 1.0000x reference)
#include <cuda_runtime.h>
#include <cuda_bf16.h>
#include <cstdint>
#include <math.h>

#define BB 64
#define TT 512
#define DD 512
#define HH 1024
#define G4 4096
#define NBLK 128

#define LBLK 8192                 // h block (32 k x 64 batch, hi+lo) in B-fragment order

// ---------------- device scratch ----------------
__device__ float g_xg[(size_t)BB * TT * G4];
__device__ __align__(1024) unsigned char g_hA[4][32 * LBLK]; // h, 4 parities x 32 blocks
__device__ unsigned g_ready[4][32];
__device__ __align__(1024) unsigned char g_xA[(size_t)256 * 8 * 32768];
__device__ __align__(1024) unsigned char g_wA[(size_t)32 * 8 * 32768];

// ---------------- helpers ----------------
__device__ __forceinline__ unsigned smem_u32(const void* p) {
    return (unsigned)__cvta_generic_to_shared(p);
}
__device__ __forceinline__ void mbar_init(unsigned a, unsigned n) {
    asm volatile("mbarrier.init.shared.b64 [%0], %1;" :: "r"(a), "r"(n) : "memory");
}
__device__ __forceinline__ void mbar_expect_tx(unsigned a, unsigned b) {
    asm volatile("mbarrier.arrive.expect_tx.shared.b64 _, [%0], %1;" :: "r"(a), "r"(b) : "memory");
}
__device__ __forceinline__ void mbar_wait(unsigned a, unsigned p) {
    asm volatile(
        "{\n\t.reg .pred P;\n"
        "W_%=:\n\t"
        "mbarrier.try_wait.parity.acquire.cta.shared::cta.b64 P, [%0], %1, 0x989680;\n\t"
        "@P bra D_%=;\n\t"
        "bra W_%=;\n"
        "D_%=:\n\t}" :: "r"(a), "r"(p) : "memory");
}
__device__ __forceinline__ void bulk_cp(void* sdst, const void* gsrc, unsigned bytes, unsigned mbar) {
    unsigned d = smem_u32(sdst);
    asm volatile(
        "cp.async.bulk.shared::cluster.global.mbarrier::complete_tx::bytes [%0], [%1], %2, [%3];"
        :: "r"(d), "l"(gsrc), "r"(bytes), "r"(mbar) : "memory");
}
__device__ __forceinline__ void mma_bf16(float* c, unsigned a0, unsigned a1, unsigned a2, unsigned a3,
                                         unsigned b0, unsigned b1) {
    asm volatile(
        "mma.sync.aligned.m16n8k16.row.col.f32.bf16.bf16.f32 "
        "{%0,%1,%2,%3}, {%4,%5,%6,%7}, {%8,%9}, {%0,%1,%2,%3};"
        : "+f"(c[0]), "+f"(c[1]), "+f"(c[2]), "+f"(c[3])
        : "r"(a0), "r"(a1), "r"(a2), "r"(a3), "r"(b0), "r"(b1));
}
__device__ __forceinline__ unsigned pack_hi(float v0, float v1, float& l0, float& l1) {
    __nv_bfloat16 h0 = __float2bfloat16_rn(v0), h1 = __float2bfloat16_rn(v1);
    l0 = v0 - __bfloat162float(h0);
    l1 = v1 - __bfloat162float(h1);
    unsigned short u0 = *(unsigned short*)&h0, u1 = *(unsigned short*)&h1;
    return (unsigned)u0 | ((unsigned)u1 << 16);
}
__device__ __forceinline__ unsigned pack_lo(float l0, float l1) {
    __nv_bfloat16 a = __float2bfloat16_rn(l0), b = __float2bfloat16_rn(l1);
    unsigned short u0 = *(unsigned short*)&a, u1 = *(unsigned short*)&b;
    return (unsigned)u0 | ((unsigned)u1 << 16);
}
__device__ __forceinline__ float fsigm(float x) { return 1.f / (1.f + __expf(-x)); }
__device__ __forceinline__ float ftanh(float x) {
    float t = __expf(-2.f * fabsf(x));
    float r = (1.f - t) / (1.f + t);
    return copysignf(r, x);
}
__device__ __forceinline__ unsigned swz(unsigned off) { return off ^ ((off >> 3) & 0x70); }
__device__ __forceinline__ unsigned sadr(int row, int slot, int tig) {
    return (unsigned)(row * 128 + ((slot ^ (row & 7)) << 4) + tig * 4);
}
__device__ __forceinline__ void flag_wait(const unsigned* f, unsigned target) {
    while (*(volatile const unsigned*)f < target) { __nanosleep(32); }
}

// ---------------- lead kernel: zero ready flags ----------------
__global__ void z0() {
    int i = threadIdx.x;
    if (i < 128) ((unsigned*)g_ready)[i] = 0u;
}

// ---------------- cvt (unchanged) ----------------
#define XN8 (BB * TT * DD / 8)
#define WN8 (G4 * DD / 8)
__global__ void cvt(const float* __restrict__ X, const float* __restrict__ Wih) {
    size_t i = (size_t)blockIdx.x * 256 + threadIdx.x;
    if (i >= XN8 + WN8) return;
    const float* src;
    unsigned char* tile;
    size_t e;
    int r, cb;
    if (i < XN8) {
        e = i * 8;
        int rg = (int)(e >> 9);
        int k = (int)(e & 511);
        tile = g_xA + ((size_t)((rg >> 7) * 8 + (k >> 6))) * 32768;
        src = X;
        r = rg & 127; cb = (k & 63) * 2;
    } else {
        e = (i - XN8) * 8;
        int ng = (int)(e >> 9);
        int k = (int)(e & 511);
        tile = g_wA + ((size_t)((ng >> 7) * 8 + (k >> 6))) * 32768;
        src = Wih;
        r = ng & 127; cb = (k & 63) * 2;
    }
    float4 v0 = *(const float4*)(src + e);
    float4 v1 = *(const float4*)(src + e + 4);
    float l0, l1, l2, l3, l4, l5, l6, l7;
    unsigned h0 = pack_hi(v0.x, v0.y, l0, l1), h1 = pack_hi(v0.z, v0.w, l2, l3);
    unsigned h2 = pack_hi(v1.x, v1.y, l4, l5), h3 = pack_hi(v1.z, v1.w, l6, l7);
    *(uint4*)(tile + swz((unsigned)(r * 128 + cb))) = make_uint4(h0, h1, h2, h3);
    *(uint4*)(tile + swz((unsigned)((r + 128) * 128 + cb))) =
        make_uint4(pack_lo(l0, l1), pack_lo(l2, l3), pack_lo(l4, l5), pack_lo(l6, l7));
}

// ---------------- xg HMMA GEMM (unchanged) ----------------
#define XBUF 65536
#define XSMEM (2 * XBUF)

__global__ __launch_bounds__(256, 1)
void xg_tc(const float* __restrict__ bih, const float* __restrict__ bhh) {
    extern __shared__ __align__(128) char xsm[];
    __shared__ __align__(8) unsigned long long xmb[2];

    int tid = threadIdx.x;
    int w = tid >> 5, lane = tid & 31;
    int g = lane >> 2, tig = lane & 3;
    int wm = w & 3, wn = w >> 2;
    int bn = blockIdx.x, bm = blockIdx.y;

    unsigned mb[2] = { smem_u32(&xmb[0]), smem_u32(&xmb[1]) };
    if (tid == 0) { mbar_init(mb[0], 1); mbar_init(mb[1], 1); }
    __syncthreads();

    const unsigned char* asrc = g_xA + (size_t)bm * 8 * 32768;
    const unsigned char* bsrc = g_wA + (size_t)bn * 8 * 32768;

    auto stage = [&](int buf, int ch) {
        if (tid == 0) {
            mbar_expect_tx(mb[buf], 65536u);
            bulk_cp(xsm + buf * XBUF, asrc + ch * 32768, 32768u, mb[buf]);
            bulk_cp(xsm + buf * XBUF + 32768, bsrc + ch * 32768, 32768u, mb[buf]);
        }
    };

    float acc[2][8][4];
#pragma unroll
    for (int mf = 0; mf < 2; mf++)
#pragma unroll
        for (int nf = 0; nf < 8; nf++)
#pragma unroll
            for (int i = 0; i < 4; i++) acc[mf][nf][i] = 0.f;

    stage(0, 0);
    stage(1, 1);
    unsigned cnt[2] = {1, 1};

    for (int ch = 0; ch < 8; ch++) {
        int buf = ch & 1;
        mbar_wait(mb[buf], (cnt[buf] - 1) & 1);
        const char* Ab = xsm + buf * XBUF;
        const char* Bb = Ab + 32768;

#pragma unroll
        for (int ks = 0; ks < 4; ks++) {
            unsigned ah[2][4], al[2][4];
#pragma unroll
            for (int mf = 0; mf < 2; mf++) {
                int rh = wm * 32 + mf * 16 + g;
                ah[mf][0] = *(const unsigned*)(Ab + sadr(rh,       ks * 2,     tig));
                ah[mf][2] = *(const unsigned*)(Ab + sadr(rh,       ks * 2 + 1, tig));
                ah[mf][1] = *(const unsigned*)(Ab + sadr(rh + 8,   ks * 2,     tig));
                ah[mf][3] = *(const unsigned*)(Ab + sadr(rh + 8,   ks * 2 + 1, tig));
                al[mf][0] = *(const unsigned*)(Ab + sadr(rh + 128, ks * 2,     tig));
                al[mf][2] = *(const unsigned*)(Ab + sadr(rh + 128, ks * 2 + 1, tig));
                al[mf][1] = *(const unsigned*)(Ab + sadr(rh + 136, ks * 2,     tig));
                al[mf][3] = *(const unsigned*)(Ab + sadr(rh + 136, ks * 2 + 1, tig));
            }
#pragma unroll
            for (int nf = 0; nf < 8; nf++) {
                int rn = wn * 64 + nf * 8 + g;
                unsigned bh0 = *(const unsigned*)(Bb + sadr(rn,       ks * 2,     tig));
                unsigned bh1 = *(const unsigned*)(Bb + sadr(rn,       ks * 2 + 1, tig));
                unsigned bl0 = *(const unsigned*)(Bb + sadr(rn + 128, ks * 2,     tig));
                unsigned bl1 = *(const unsigned*)(Bb + sadr(rn + 128, ks * 2 + 1, tig));
#pragma unroll
                for (int mf = 0; mf < 2; mf++) {
                    mma_bf16(acc[mf][nf], ah[mf][0], ah[mf][1], ah[mf][2], ah[mf][3], bh0, bh1);
                    mma_bf16(acc[mf][nf], ah[mf][0], ah[mf][1], ah[mf][2], ah[mf][3], bl0, bl1);
                    mma_bf16(acc[mf][nf], al[mf][0], al[mf][1], al[mf][2], al[mf][3], bh0, bh1);
                }
            }
        }
        __syncthreads();
        if (ch + 2 < 8) {
            stage(buf, ch + 2);
            cnt[buf]++;
        }
    }

#pragma unroll
    for (int nf = 0; nf < 8; nf++) {
        int col = bn * 128 + wn * 64 + nf * 8 + tig * 2;
        float bb0 = bih[col] + bhh[col];
        float bb1 = bih[col + 1] + bhh[col + 1];
#pragma unroll
        for (int mf = 0; mf < 2; mf++) {
            int row = bm * 128 + wm * 32 + mf * 16 + g;
            *(float2*)(g_xg + (size_t)row * G4 + col) =
                make_float2(acc[mf][nf][0] + bb0, acc[mf][nf][1] + bb1);
            *(float2*)(g_xg + (size_t)(row + 8) * G4 + col) =
                make_float2(acc[mf][nf][2] + bb0, acc[mf][nf][3] + bb1);
        }
    }
}

// ---------------- persistent HMMA LSTM: register-resident W (A = W, B = h) ----------------
// 256 threads / 8 warps; warp w owns k-slice [128w, 128w+128) = blocks 4w..4w+3.
// SMEM: 16 buffers x 8192 = 131072 (stash [8][32][68] f32 aliases it).
#define SMEM_BYTES (131072 + 1024)
#define STASH_STRIDE 68

__global__ __launch_bounds__(256, 1)
void lstm_tc(const float* __restrict__ Whh, const int* __restrict__ mask,
             const float* __restrict__ h0, const float* __restrict__ c0,
             float* __restrict__ out) {
    extern __shared__ char smraw[];
    char* smb = (char*)(((uintptr_t)smraw + 1023) & ~(uintptr_t)1023);
    float* stash = (float*)smb;             // aliases buffers

    __shared__ __align__(8) unsigned long long mbst[16];   // full barriers, 2 per warp

    int tid = threadIdx.x;
    int w = tid >> 5, lane = tid & 31;
    int g = lane >> 2, tig = lane & 3;
    int bid = blockIdx.x;
    int base = bid * 8;
    int gb_own = base >> 5;
    int eu = tid & 7;
    int eb0 = tid >> 3;                      // cells: (eb0, eu) and (eb0+32, eu)

    unsigned mbF[2] = { smem_u32(&mbst[w * 2]), smem_u32(&mbst[w * 2 + 1]) };
    if (tid == 0)
#pragma unroll
        for (int i = 0; i < 16; i++) mbar_init(smem_u32(&mbst[i]), 1);

    // ---- load W into registers (A fragments, hi/lo), once ----
    unsigned WH[2][8][4], WL[2][8][4];
#pragma unroll
    for (int mf = 0; mf < 2; mf++) {
        int m0 = mf * 16 + g;
        int m1 = m0 + 8;
        const float* r0 = Whh + ((size_t)((m0 >> 3) * HH + base + (m0 & 7))) * HH;
        const float* r1 = Whh + ((size_t)((m1 >> 3) * HH + base + (m1 & 7))) * HH;
#pragma unroll
        for (int kf = 0; kf < 8; kf++) {
            int k0 = w * 128 + kf * 16 + tig * 2;
            float l0, l1;
            WH[mf][kf][0] = pack_hi(r0[k0],     r0[k0 + 1], l0, l1); WL[mf][kf][0] = pack_lo(l0, l1);
            WH[mf][kf][1] = pack_hi(r1[k0],     r1[k0 + 1], l0, l1); WL[mf][kf][1] = pack_lo(l0, l1);
            WH[mf][kf][2] = pack_hi(r0[k0 + 8], r0[k0 + 9], l0, l1); WL[mf][kf][2] = pack_lo(l0, l1);
            WH[mf][kf][3] = pack_hi(r1[k0 + 8], r1[k0 + 9], l0, l1); WL[mf][kf][3] = pack_lo(l0, l1);
        }
    }

    // ---- per-thread state: 2 cells ----
    float creg[2], hreg[2];
    unsigned eoff[2];
    {
        int kb0 = (base & 31) + eu;
        int kf2 = kb0 >> 4, kk = kb0 & 15;
#pragma unroll
        for (int cc = 0; cc < 2; cc++) {
            int eb = eb0 + cc * 32;
            creg[cc] = c0[base + eu];
            hreg[cc] = h0[base + eu];
            int nf = eb >> 3, nn = eb & 7;
            int lt = nn * 4 + ((kk & 7) >> 1);
            eoff[cc] = (unsigned)(((kf2 * 8 + nf) * 2) * 256 + lt * 8 + (kk >> 3) * 4 + (kk & 1) * 2);
            __nv_bfloat16 hh = __float2bfloat16_rn(hreg[cc]);
            float lo = hreg[cc] - __bfloat162float(hh);
            __nv_bfloat16 hl = __float2bfloat16_rn(lo);
            unsigned char* blk = g_hA[0] + gb_own * LBLK;
            *(__nv_bfloat16*)(blk + eoff[cc]) = hh;
            *(__nv_bfloat16*)(blk + eoff[cc] + 256) = hl;
        }
    }
    __syncthreads();
    if (tid == 0) {
        __threadfence();
        atomicAdd(&g_ready[0][gb_own], 1u);
    }

    unsigned ccnt[2] = {0, 0};   // fill==consume count per buffer (same warp)

    for (int t = 0; t < TT; t++) {
        const unsigned char* src = g_hA[t & 3];
        unsigned rdy_target = 4u * (unsigned)(t / 4 + 1);
        const unsigned* rdy = g_ready[t & 3];

        // ---- prologue: this warp stages its first two blocks ----
        if (lane == 0) {
#pragma unroll
            for (int d = 0; d < 2; d++) {
                int gb = w * 4 + d;
                flag_wait(&rdy[gb], rdy_target);
                mbar_expect_tx(mbF[d], (unsigned)LBLK);
                bulk_cp(smb + (size_t)(w * 2 + d) * LBLK, src + (size_t)gb * LBLK, (unsigned)LBLK, mbF[d]);
            }
        }

        // ---- prefetch xg + mask (2 cells) ----
        float xgv[2][4];
        int mk[2];
#pragma unroll
        for (int cc = 0; cc < 2; cc++) {
            int eb = eb0 + cc * 32;
            const float* xp = g_xg + ((size_t)eb * TT + t) * G4 + base + eu;
#pragma unroll
            for (int gg = 0; gg < 4; gg++) xgv[cc][gg] = __ldg(xp + gg * HH);
            mk[cc] = __ldg(mask + eb * TT + t);
        }

        float acc[2][8][4];
#pragma unroll
        for (int mf = 0; mf < 2; mf++)
#pragma unroll
            for (int nf = 0; nf < 8; nf++)
#pragma unroll
                for (int i = 0; i < 4; i++) acc[mf][nf][i] = 0.f;

        // ---- K stream: 4 blocks, warp-private, depth 2 ----
        for (int j = 0; j < 4; j++) {
            int d = j & 1;
            mbar_wait(mbF[d], ccnt[d] & 1);
            ccnt[d]++;
            const char* Ab = smb + (size_t)(w * 2 + d) * LBLK;

#pragma unroll
            for (int kf2 = 0; kf2 < 2; kf2++) {
                int kf = j * 2 + kf2;
#pragma unroll
                for (int nf = 0; nf < 8; nf++) {
                    const char* bp = Ab + ((kf2 * 8 + nf) * 2) * 256 + lane * 8;
                    uint2 BH = *(const uint2*)bp;
                    uint2 BL = *(const uint2*)(bp + 256);
#pragma unroll
                    for (int mf = 0; mf < 2; mf++) {
                        mma_bf16(acc[mf][nf], WH[mf][kf][0], WH[mf][kf][1], WH[mf][kf][2], WH[mf][kf][3], BH.x, BH.y);
                        mma_bf16(acc[mf][nf], WH[mf][kf][0], WH[mf][kf][1], WH[mf][kf][2], WH[mf][kf][3], BL.x, BL.y);
                        mma_bf16(acc[mf][nf], WL[mf][kf][0], WL[mf][kf][1], WL[mf][kf][2], WL[mf][kf][3], BH.x, BH.y);
                    }
                }
            }

            // restage same buffer (warp-synchronous: all LDS of round j done)
            if (j + 2 < 4 && lane == 0) {
                int gb = w * 4 + j + 2;
                flag_wait(&rdy[gb], rdy_target);
                mbar_expect_tx(mbF[d], (unsigned)LBLK);
                bulk_cp(smb + (size_t)(w * 2 + d) * LBLK, src + (size_t)gb * LBLK, (unsigned)LBLK, mbF[d]);
            }
        }

        // ---- cross-warp reduction via stash (aliases buffers: sync first) ----
        __syncthreads();
#pragma unroll
        for (int mf = 0; mf < 2; mf++)
#pragma unroll
            for (int nf = 0; nf < 8; nf++) {
                int m = mf * 16 + g;
                int n = nf * 8 + tig * 2;
                *(float2*)&stash[((size_t)w * 32 + m) * STASH_STRIDE + n] =
                    make_float2(acc[mf][nf][0], acc[mf][nf][1]);
                *(float2*)&stash[((size_t)w * 32 + m + 8) * STASH_STRIDE + n] =
                    make_float2(acc[mf][nf][2], acc[mf][nf][3]);
            }
        __syncthreads();

        // ---- epilogue: 2 cells per thread ----
#pragma unroll
        for (int cc = 0; cc < 2; cc++) {
            int eb = eb0 + cc * 32;
            float gi = xgv[cc][0], gf = xgv[cc][1], gG = xgv[cc][2], go = xgv[cc][3];
#pragma unroll
            for (int ww = 0; ww < 8; ww++) {
                const float* sp = stash + (size_t)ww * 32 * STASH_STRIDE + eb;
                gi += sp[(0 * 8 + eu) * STASH_STRIDE];
                gf += sp[(1 * 8 + eu) * STASH_STRIDE];
                gG += sp[(2 * 8 + eu) * STASH_STRIDE];
                go += sp[(3 * 8 + eu) * STASH_STRIDE];
            }
            float iv = fsigm(gi);
            float fv = fsigm(gf);
            float gv = ftanh(gG);
            float ov = fsigm(go);
            float cn = fv * creg[cc] + iv * gv;
            float hn = ov * ftanh(cn);
            creg[cc] = mk[cc] ? cn : creg[cc];
            hn       = mk[cc] ? hn : hreg[cc];
            hreg[cc] = hn;
            out[((size_t)eb * TT + t) * HH + base + eu] = hn;
            __nv_bfloat16 hh = __float2bfloat16_rn(hn);
            float lo = hn - __bfloat162float(hh);
            __nv_bfloat16 hl = __float2bfloat16_rn(lo);
            unsigned char* blk = g_hA[(t + 1) & 3] + gb_own * LBLK;
            *(__nv_bfloat16*)(blk + eoff[cc]) = hh;
            *(__nv_bfloat16*)(blk + eoff[cc] + 256) = hl;
        }

        // ---- post readiness of this CTA's slice of h(t+1) ----
        __syncthreads();
        if (tid == 0) {
            __threadfence();
            atomicAdd(&g_ready[(t + 1) & 3][gb_own], 1u);
        }
    }
}

// ---------------- launch ----------------
extern "C" void kernel_launch(void* const* d_in, const int* in_sizes, int n_in,
                              void* d_out, int out_size) {
    const float* x    = (const float*)d_in[0];
    const int*   mask = (const int*)  d_in[1];
    const float* Wih  = (const float*)d_in[2];
    const float* Whh  = (const float*)d_in[3];
    const float* bih  = (const float*)d_in[4];
    const float* bhh  = (const float*)d_in[5];
    const float* h0   = (const float*)d_in[6];
    const float* c0   = (const float*)d_in[7];
    float* out = (float*)d_out;

    cudaFuncSetAttribute(xg_tc, cudaFuncAttributeMaxDynamicSharedMemorySize, XSMEM);
    cudaFuncSetAttribute(lstm_tc, cudaFuncAttributeMaxDynamicSharedMemorySize, SMEM_BYTES);

    z0<<<1, 128>>>();
    cvt<<<(XN8 + WN8 + 255) / 256, 256>>>(x, Wih);
    xg_tc<<<dim3(G4 / 128, (BB * TT) / 128), 256, XSMEM>>>(bih, bhh);
    lstm_tc<<<NBLK, 256, SMEM_BYTES>>>(Whh, mask, h0, c0, out);
}